// round 2
// baseline (speedup 1.0000x reference)
#include <cuda_runtime.h>
#include <cstdint>

// Problem constants (fixed by the dataset).
#define NN 100000
#define EE 1600000
#define EPE (EE + NN)          // edges incl. self-loops
#define NEG_SLOPE 0.2f

// ---------------------------------------------------------------------------
// Scratch (static device globals; no allocations allowed).
// ---------------------------------------------------------------------------
__device__ float g_xlr1[(size_t)NN * 128];   // [n][0:64]=xl1, [64:128]=xr1
__device__ float g_ex[(size_t)EPE * 4];      // per-edge exp(score), 4 heads
__device__ float g_denom[(size_t)NN * 4];    // softmax denominators
__device__ float g_agg1[(size_t)NN * 64];    // layer1 aggregate (pre bias/relu)
__device__ float g_xlr2[(size_t)NN * 512];   // [n][0:256]=xl2, [256:512]=xr2
__device__ float g_agg2[(size_t)NN * 256];   // layer2 aggregate per (head, c)
__device__ int   g_src[EPE];                 // decoded edge sources (+self loops)
__device__ int   g_dst[EPE];                 // decoded edge destinations
__device__ int   g_is64;                     // 1 if edge_index buffer is int64

__device__ __forceinline__ void red_add_v4(float* p, float a, float b, float c, float d) {
    asm volatile("red.global.add.v4.f32 [%0], {%1,%2,%3,%4};"
                 :: "l"(p), "f"(a), "f"(b), "f"(c), "f"(d) : "memory");
}

// ---------------------------------------------------------------------------
// Edge-index dtype detection + decode (+ self-loop append).
// ---------------------------------------------------------------------------
__global__ void flag_init_kernel() { g_is64 = 1; }

#define DETECT_SAMPLES 65536   // 64K int64 reads = 512KB, within either buffer
__global__ void detect_kernel(const long long* __restrict__ ei) {
    int i = blockIdx.x * blockDim.x + threadIdx.x;
    if (i < DETECT_SAMPLES) {
        long long v = ei[i];
        if (v < 0 || v >= NN) g_is64 = 0;   // racy plain store is fine (same value)
    }
}

__global__ void convert_kernel(const void* __restrict__ ei) {
    int i = blockIdx.x * blockDim.x + threadIdx.x;
    if (i >= EPE) return;
    if (i >= EE) { g_src[i] = i - EE; g_dst[i] = i - EE; return; }
    if (g_is64) {
        g_src[i] = (int)((const long long*)ei)[i];
        g_dst[i] = (int)((const long long*)ei)[EE + i];
    } else {
        g_src[i] = ((const int*)ei)[i];
        g_dst[i] = ((const int*)ei)[EE + i];
    }
}

// ---------------------------------------------------------------------------
// Zero kernels (denoms + aggregation buffers must be fresh each call).
// ---------------------------------------------------------------------------
__global__ void zero1_kernel() {  // g_denom + g_agg1
    int i = blockIdx.x * blockDim.x + threadIdx.x;
    float4 z = make_float4(0.f, 0.f, 0.f, 0.f);
    if (i < NN) ((float4*)g_denom)[i] = z;
    if (i < NN * 16) ((float4*)g_agg1)[i] = z;
}

__global__ void zero2_kernel() {  // g_denom + g_agg2
    int i = blockIdx.x * blockDim.x + threadIdx.x;
    float4 z = make_float4(0.f, 0.f, 0.f, 0.f);
    if (i < NN) ((float4*)g_denom)[i] = z;
    if (i < NN * 64) ((float4*)g_agg2)[i] = z;
}

// ---------------------------------------------------------------------------
// Dual GEMM: Y[n][j] = X[n][:] @ [W1 | W2][:, j] + [b1 | b2][j]
//   X: n x 64 (optionally relu(X + preBias) applied on load)
//   W1, W2: 64 x JH row-major; Y: n x (2*JH)
// Block: 256 threads, 32-row x 128-col tile.
// ---------------------------------------------------------------------------
__global__ void gemm_dual_kernel(const float* __restrict__ X, int n, int JH,
                                 const float* __restrict__ W1, const float* __restrict__ b1,
                                 const float* __restrict__ W2, const float* __restrict__ b2,
                                 const float* __restrict__ preBias,
                                 float* __restrict__ Y) {
    __shared__ float Wsm[64 * 128];
    __shared__ float Xs[32 * 64];
    const int tid = threadIdx.x;
    const int jt = blockIdx.y;
    const int row0 = blockIdx.x * 32;
    const int J = 2 * JH;

#pragma unroll
    for (int t = 0; t < 32; t++) {
        int i = tid + t * 256;
        int k = i >> 7, jj = i & 127;
        int j = jt * 128 + jj;
        Wsm[i] = (j < JH) ? W1[k * JH + j] : W2[k * JH + (j - JH)];
    }
#pragma unroll
    for (int t = 0; t < 8; t++) {
        int i = tid + t * 256;
        int r = i >> 6, k = i & 63;
        int row = row0 + r;
        float v = (row < n) ? X[(size_t)row * 64 + k] : 0.f;
        if (preBias) { v += preBias[k]; v = fmaxf(v, 0.f); }
        Xs[i] = v;
    }
    __syncthreads();

    const int cg = tid & 31, rg = tid >> 5;
    const int c0 = cg * 4;
    const int rbase = rg * 4;

    float4 bias;
    {
        int j = jt * 128 + c0;
        const float* bb = (j < JH) ? (b1 + j) : (b2 + (j - JH));
        bias = make_float4(bb[0], bb[1], bb[2], bb[3]);
    }
    float4 acc0 = bias, acc1 = bias, acc2 = bias, acc3 = bias;

#pragma unroll
    for (int k = 0; k < 64; k++) {
        float4 w = *(const float4*)&Wsm[k * 128 + c0];
        float x0 = Xs[(rbase + 0) * 64 + k];
        float x1 = Xs[(rbase + 1) * 64 + k];
        float x2 = Xs[(rbase + 2) * 64 + k];
        float x3 = Xs[(rbase + 3) * 64 + k];
        acc0.x += x0 * w.x; acc0.y += x0 * w.y; acc0.z += x0 * w.z; acc0.w += x0 * w.w;
        acc1.x += x1 * w.x; acc1.y += x1 * w.y; acc1.z += x1 * w.z; acc1.w += x1 * w.w;
        acc2.x += x2 * w.x; acc2.y += x2 * w.y; acc2.z += x2 * w.z; acc2.w += x2 * w.w;
        acc3.x += x3 * w.x; acc3.y += x3 * w.y; acc3.z += x3 * w.z; acc3.w += x3 * w.w;
    }

    float4 accs[4] = {acc0, acc1, acc2, acc3};
#pragma unroll
    for (int r = 0; r < 4; r++) {
        int row = row0 + rbase + r;
        if (row < n)
            *(float4*)&Y[(size_t)row * J + jt * 128 + c0] = accs[r];
    }
}

// ---------------------------------------------------------------------------
// Layer 1 edge score + exp + denom.  One thread per (edge, head).  C=16.
// ---------------------------------------------------------------------------
__global__ void score1_kernel(const float* __restrict__ att) {
    __shared__ float a_s[64];
    if (threadIdx.x < 64) a_s[threadIdx.x] = att[threadIdx.x];
    __syncthreads();
    int idx = blockIdx.x * blockDim.x + threadIdx.x;
    if (idx >= EPE * 4) return;
    int e = idx >> 2, h = idx & 3;
    int s = g_src[e], d = g_dst[e];

    const float4* xl = (const float4*)(g_xlr1 + (size_t)s * 128 + h * 16);
    const float4* xr = (const float4*)(g_xlr1 + (size_t)d * 128 + 64 + h * 16);
    float sc = 0.f;
#pragma unroll
    for (int q = 0; q < 4; q++) {
        float4 a = xl[q], b = xr[q];
        float v;
        v = a.x + b.x; v = v > 0.f ? v : NEG_SLOPE * v; sc += v * a_s[h * 16 + q * 4 + 0];
        v = a.y + b.y; v = v > 0.f ? v : NEG_SLOPE * v; sc += v * a_s[h * 16 + q * 4 + 1];
        v = a.z + b.z; v = v > 0.f ? v : NEG_SLOPE * v; sc += v * a_s[h * 16 + q * 4 + 2];
        v = a.w + b.w; v = v > 0.f ? v : NEG_SLOPE * v; sc += v * a_s[h * 16 + q * 4 + 3];
    }
    float ex = __expf(sc);
    g_ex[(size_t)e * 4 + h] = ex;
    atomicAdd(&g_denom[(size_t)d * 4 + h], ex);
}

// ---------------------------------------------------------------------------
// Layer 1 aggregation: agg1[dst] += (ex/denom) * xl1[src].  16 threads/edge.
// ---------------------------------------------------------------------------
__global__ void agg1_kernel() {
    int idx = blockIdx.x * blockDim.x + threadIdx.x;
    if (idx >= EPE * 16) return;
    int e = idx >> 4, g = idx & 15;
    int h = g >> 2;
    int s = g_src[e], d = g_dst[e];

    float w = g_ex[(size_t)e * 4 + h] / g_denom[(size_t)d * 4 + h];
    float4 v = *(const float4*)(g_xlr1 + (size_t)s * 128 + g * 4);
    red_add_v4(g_agg1 + (size_t)d * 64 + g * 4, w * v.x, w * v.y, w * v.z, w * v.w);
}

// ---------------------------------------------------------------------------
// Layer 2 edge score.  One warp per edge; lane -> (head = lane/8, part = lane%8),
// each part covers 8 of the 64 channels.  C=64.
// ---------------------------------------------------------------------------
__global__ void score2_kernel(const float* __restrict__ att) {
    __shared__ float a_s[256];
    a_s[threadIdx.x] = att[threadIdx.x];
    __syncthreads();
    int t = blockIdx.x * blockDim.x + threadIdx.x;
    int e = t >> 5, lane = t & 31;
    if (e >= EPE) return;
    int h = lane >> 3, part = lane & 7;
    int s = g_src[e], d = g_dst[e];

    const float4* xl = (const float4*)(g_xlr2 + (size_t)s * 512 + h * 64 + part * 8);
    const float4* xr = (const float4*)(g_xlr2 + (size_t)d * 512 + 256 + h * 64 + part * 8);
    float sc = 0.f;
#pragma unroll
    for (int q = 0; q < 2; q++) {
        float4 a = xl[q], b = xr[q];
        int ab = h * 64 + part * 8 + q * 4;
        float v;
        v = a.x + b.x; v = v > 0.f ? v : NEG_SLOPE * v; sc += v * a_s[ab + 0];
        v = a.y + b.y; v = v > 0.f ? v : NEG_SLOPE * v; sc += v * a_s[ab + 1];
        v = a.z + b.z; v = v > 0.f ? v : NEG_SLOPE * v; sc += v * a_s[ab + 2];
        v = a.w + b.w; v = v > 0.f ? v : NEG_SLOPE * v; sc += v * a_s[ab + 3];
    }
    sc += __shfl_down_sync(0xffffffffu, sc, 4, 8);
    sc += __shfl_down_sync(0xffffffffu, sc, 2, 8);
    sc += __shfl_down_sync(0xffffffffu, sc, 1, 8);
    if (part == 0) {
        float ex = __expf(sc);
        g_ex[(size_t)e * 4 + h] = ex;
        atomicAdd(&g_denom[(size_t)d * 4 + h], ex);
    }
}

// ---------------------------------------------------------------------------
// Layer 2 aggregation: agg2[dst][h][c] += (ex/denom)*xl2[src][h][c].  Warp/edge.
// ---------------------------------------------------------------------------
__global__ void agg2_kernel() {
    int t = blockIdx.x * blockDim.x + threadIdx.x;
    int e = t >> 5, lane = t & 31;
    if (e >= EPE) return;
    int h = lane >> 3;
    int s = g_src[e], d = g_dst[e];

    float w = g_ex[(size_t)e * 4 + h] / g_denom[(size_t)d * 4 + h];
    const float4* xl = (const float4*)(g_xlr2 + (size_t)s * 512 + lane * 8);
    float* outp = g_agg2 + (size_t)d * 256 + lane * 8;
    float4 v0 = xl[0], v1 = xl[1];
    red_add_v4(outp,     w * v0.x, w * v0.y, w * v0.z, w * v0.w);
    red_add_v4(outp + 4, w * v1.x, w * v1.y, w * v1.z, w * v1.w);
}

// ---------------------------------------------------------------------------
// Final: out[n][c] = relu(mean_h(agg2[n][h][c]) + bo2[c])
// ---------------------------------------------------------------------------
__global__ void final_kernel(const float* __restrict__ bo2, float* __restrict__ out) {
    int idx = blockIdx.x * blockDim.x + threadIdx.x;
    if (idx >= NN * 64) return;
    int n = idx >> 6, c = idx & 63;
    const float* a = g_agg2 + (size_t)n * 256 + c;
    float v = 0.25f * (a[0] + a[64] + a[128] + a[192]) + bo2[c];
    out[idx] = fmaxf(v, 0.f);
}

// ---------------------------------------------------------------------------
// Launch
// ---------------------------------------------------------------------------
extern "C" void kernel_launch(void* const* d_in, const int* in_sizes, int n_in,
                              void* d_out, int out_size) {
    const float* x   = (const float*)d_in[0];
    const void*  ei  = d_in[1];
    // d_in[2]: frame_mask (unused — all ones, and unused by reference math)
    const float* Wl1 = (const float*)d_in[3];
    const float* bl1 = (const float*)d_in[4];
    const float* Wr1 = (const float*)d_in[5];
    const float* br1 = (const float*)d_in[6];
    const float* att1 = (const float*)d_in[7];
    const float* bo1 = (const float*)d_in[8];
    const float* Wl2 = (const float*)d_in[9];
    const float* bl2 = (const float*)d_in[10];
    const float* Wr2 = (const float*)d_in[11];
    const float* br2 = (const float*)d_in[12];
    const float* att2 = (const float*)d_in[13];
    const float* bo2 = (const float*)d_in[14];
    float* out = (float*)d_out;

    float *p_xlr1 = nullptr, *p_agg1 = nullptr, *p_xlr2 = nullptr;
    cudaGetSymbolAddress((void**)&p_xlr1, g_xlr1);
    cudaGetSymbolAddress((void**)&p_agg1, g_agg1);
    cudaGetSymbolAddress((void**)&p_xlr2, g_xlr2);

    // Decode edge_index (dtype-agnostic) + self-loops
    flag_init_kernel<<<1, 1>>>();
    detect_kernel<<<(DETECT_SAMPLES + 255) / 256, 256>>>((const long long*)ei);
    convert_kernel<<<(EPE + 255) / 256, 256>>>(ei);

    // Layer 1
    zero1_kernel<<<(NN * 16 + 255) / 256, 256>>>();
    {
        dim3 grid((NN + 31) / 32, 1);
        gemm_dual_kernel<<<grid, 256>>>(x, NN, 64, Wl1, bl1, Wr1, br1, nullptr, p_xlr1);
    }
    score1_kernel<<<(EPE * 4 + 255) / 256, 256>>>(att1);
    agg1_kernel<<<(EPE * 16 + 255) / 256, 256>>>();

    // Layer 2 (relu(agg1 + bo1) folded into GEMM input load)
    {
        dim3 grid((NN + 31) / 32, 4);
        gemm_dual_kernel<<<grid, 256>>>(p_agg1, NN, 256, Wl2, bl2, Wr2, br2, bo1, p_xlr2);
    }
    zero2_kernel<<<(NN * 64 + 255) / 256, 256>>>();
    score2_kernel<<<(EPE * 32 + 255) / 256, 256>>>(att2);
    agg2_kernel<<<(EPE * 32 + 255) / 256, 256>>>();
    final_kernel<<<(NN * 64 + 255) / 256, 256>>>(bo2, out);
}

// round 3
// speedup vs baseline: 2.7271x; 2.7271x over previous
#include <cuda_runtime.h>
#include <cstdint>

// Problem constants (fixed by the dataset).
#define NN 100000
#define EE 1600000
#define EPE (EE + NN)          // edges incl. self-loops
#define NEG_SLOPE 0.2f
#define NB 98                  // scan blocks: ceil(100000/1024)

// ---------------------------------------------------------------------------
// Scratch (static device globals; no allocations allowed).
// ---------------------------------------------------------------------------
__device__ float g_xlr1[(size_t)NN * 128];   // [n][0:64]=xl1, [64:128]=xr1
__device__ float g_agg1[(size_t)NN * 64];    // layer1 output (pre bias/relu)
__device__ float g_xlr2[(size_t)NN * 512];   // [n][0:256]=xl2, [256:512]=xr2
__device__ int   g_src[EPE], g_dst[EPE];     // decoded edges (+self loops)
__device__ int   g_ssrc[EPE];                // srcs sorted by dst (CSR payload)
__device__ int   g_deg[NN], g_cur[NN];
__device__ int   g_off[NN + 1];              // CSR row offsets
__device__ int   g_bsum[NB], g_boff[NB];
__device__ int   g_is64;

typedef unsigned long long u64;
__device__ __forceinline__ u64 pack2(float x, float y) {
    u64 r; asm("mov.b64 %0, {%1,%2};" : "=l"(r) : "f"(x), "f"(y)); return r;
}
__device__ __forceinline__ u64 ffma2(u64 a, u64 b, u64 c) {
    u64 d; asm("fma.rn.f32x2 %0, %1, %2, %3;" : "=l"(d) : "l"(a), "l"(b), "l"(c)); return d;
}
__device__ __forceinline__ float2 unpack2(u64 v) {
    float2 f; asm("mov.b64 {%0,%1}, %2;" : "=f"(f.x), "=f"(f.y) : "l"(v)); return f;
}

// ---------------------------------------------------------------------------
// Meta init: zero degree/cursor counters, set dtype flag default.
// ---------------------------------------------------------------------------
__global__ void zero_meta_kernel() {
    int i = blockIdx.x * blockDim.x + threadIdx.x;
    if (i < NN) { g_deg[i] = 0; g_cur[i] = 0; }
    if (i == 0) g_is64 = 1;
}

#define DETECT_SAMPLES 65536
__global__ void detect_kernel(const long long* __restrict__ ei) {
    int i = blockIdx.x * blockDim.x + threadIdx.x;
    if (i < DETECT_SAMPLES) {
        long long v = ei[i];
        if (v < 0 || v >= NN) g_is64 = 0;
    }
}

// Decode edges (either dtype), append self-loops, histogram degrees by dst.
__global__ void convert_hist_kernel(const void* __restrict__ ei) {
    int i = blockIdx.x * blockDim.x + threadIdx.x;
    if (i >= EPE) return;
    int s, d;
    if (i >= EE) { s = d = i - EE; }
    else if (g_is64) {
        s = (int)((const long long*)ei)[i];
        d = (int)((const long long*)ei)[EE + i];
    } else {
        s = ((const int*)ei)[i];
        d = ((const int*)ei)[EE + i];
    }
    g_src[i] = s; g_dst[i] = d;
    atomicAdd(&g_deg[d], 1);
}

// ---------------------------------------------------------------------------
// Exclusive prefix scan of g_deg -> g_off (3 kernels).
// ---------------------------------------------------------------------------
__global__ void scan1_kernel() {          // per-block sums
    __shared__ int sm[1024];
    int t = threadIdx.x, i = blockIdx.x * 1024 + t;
    sm[t] = (i < NN) ? g_deg[i] : 0;
    __syncthreads();
    for (int ofs = 512; ofs > 0; ofs >>= 1) {
        if (t < ofs) sm[t] += sm[t + ofs];
        __syncthreads();
    }
    if (t == 0) g_bsum[blockIdx.x] = sm[0];
}

__global__ void scan2_kernel() {          // serial scan of 98 block sums
    if (threadIdx.x == 0) {
        int run = 0;
        for (int b = 0; b < NB; b++) { g_boff[b] = run; run += g_bsum[b]; }
        g_off[NN] = EPE;
    }
}

__global__ void scan3_kernel() {          // block exclusive scan + add offset
    __shared__ int sm[1024];
    int t = threadIdx.x, i = blockIdx.x * 1024 + t;
    int v = (i < NN) ? g_deg[i] : 0;
    sm[t] = v;
    __syncthreads();
    for (int ofs = 1; ofs < 1024; ofs <<= 1) {
        int x = (t >= ofs) ? sm[t - ofs] : 0;
        __syncthreads();
        sm[t] += x;
        __syncthreads();
    }
    if (i < NN) g_off[i] = g_boff[blockIdx.x] + sm[t] - v;
}

__global__ void scatter_kernel() {        // bucket srcs by dst
    int i = blockIdx.x * blockDim.x + threadIdx.x;
    if (i >= EPE) return;
    int d = g_dst[i];
    int pos = g_off[d] + atomicAdd(&g_cur[d], 1);
    g_ssrc[pos] = g_src[i];
}

// ---------------------------------------------------------------------------
// Dual GEMM with packed f32x2 FMA: Y[n][j] = X[n][:] @ [W1|W2][:, j] + [b1|b2][j]
//   X: n x 64 (optional fused relu(X + preBias)); W1,W2: 64 x JH row-major.
// Block 256 threads, 32-row x 128-col tile.
// ---------------------------------------------------------------------------
__global__ void gemm_dual_kernel(const float* __restrict__ X, int n, int JH,
                                 const float* __restrict__ W1, const float* __restrict__ b1,
                                 const float* __restrict__ W2, const float* __restrict__ b2,
                                 const float* __restrict__ preBias,
                                 float* __restrict__ Y) {
    __shared__ float Wsm[64 * 128];
    __shared__ float Xs[32 * 64];
    const int tid = threadIdx.x;
    const int jt = blockIdx.y;
    const int row0 = blockIdx.x * 32;
    const int J = 2 * JH;

#pragma unroll
    for (int t = 0; t < 32; t++) {
        int i = tid + t * 256;
        int k = i >> 7, jj = i & 127;
        int j = jt * 128 + jj;
        Wsm[i] = (j < JH) ? W1[k * JH + j] : W2[k * JH + (j - JH)];
    }
#pragma unroll
    for (int t = 0; t < 8; t++) {
        int i = tid + t * 256;
        int r = i >> 6, k = i & 63;
        int row = row0 + r;
        float v = (row < n) ? X[(size_t)row * 64 + k] : 0.f;
        if (preBias) { v += preBias[k]; v = fmaxf(v, 0.f); }
        Xs[i] = v;
    }
    __syncthreads();

    const int cg = tid & 31, rg = tid >> 5;
    const int c0 = cg * 4;
    const int rbase = rg * 4;

    u64 bias0, bias1;
    {
        int j = jt * 128 + c0;
        const float* bb = (j < JH) ? (b1 + j) : (b2 + (j - JH));
        bias0 = pack2(bb[0], bb[1]);
        bias1 = pack2(bb[2], bb[3]);
    }
    u64 acc[4][2];
#pragma unroll
    for (int r = 0; r < 4; r++) { acc[r][0] = bias0; acc[r][1] = bias1; }

#pragma unroll
    for (int k = 0; k < 64; k++) {
        const ulonglong2 w = *(const ulonglong2*)&Wsm[k * 128 + c0];
        float x0 = Xs[(rbase + 0) * 64 + k];
        float x1 = Xs[(rbase + 1) * 64 + k];
        float x2 = Xs[(rbase + 2) * 64 + k];
        float x3 = Xs[(rbase + 3) * 64 + k];
        u64 p0 = pack2(x0, x0), p1 = pack2(x1, x1);
        u64 p2 = pack2(x2, x2), p3 = pack2(x3, x3);
        acc[0][0] = ffma2(p0, w.x, acc[0][0]); acc[0][1] = ffma2(p0, w.y, acc[0][1]);
        acc[1][0] = ffma2(p1, w.x, acc[1][0]); acc[1][1] = ffma2(p1, w.y, acc[1][1]);
        acc[2][0] = ffma2(p2, w.x, acc[2][0]); acc[2][1] = ffma2(p2, w.y, acc[2][1]);
        acc[3][0] = ffma2(p3, w.x, acc[3][0]); acc[3][1] = ffma2(p3, w.y, acc[3][1]);
    }

#pragma unroll
    for (int r = 0; r < 4; r++) {
        int row = row0 + rbase + r;
        if (row < n) {
            float2 lo = unpack2(acc[r][0]), hi = unpack2(acc[r][1]);
            *(float4*)&Y[(size_t)row * J + jt * 128 + c0] =
                make_float4(lo.x, lo.y, hi.x, hi.y);
        }
    }
}

// ---------------------------------------------------------------------------
// Fused layer-1 edge pass: warp per dst.
//   out1[d][c] = (sum_e ex_e * xl1[s_e][c]) / (sum_e ex_e)
// Lane l holds channels {2l, 2l+1}; head h = l>>3 (8 lanes/head).
// ---------------------------------------------------------------------------
__global__ void fused1_kernel(const float* __restrict__ att) {
    int d = blockIdx.x * 8 + (threadIdx.x >> 5);
    if (d >= NN) return;
    int lane = threadIdx.x & 31;

    float2 xr = *(const float2*)(g_xlr1 + (size_t)d * 128 + 64 + lane * 2);
    float a0 = __ldg(att + lane * 2), a1 = __ldg(att + lane * 2 + 1);

    int e0 = g_off[d], e1 = g_off[d + 1];
    float acc0 = 0.f, acc1 = 0.f, den = 0.f;
    for (int e = e0; e < e1; e++) {
        int s = g_ssrc[e];
        float2 xl = *(const float2*)(g_xlr1 + (size_t)s * 128 + lane * 2);
        float v0 = xl.x + xr.x; v0 = v0 > 0.f ? v0 : NEG_SLOPE * v0;
        float v1 = xl.y + xr.y; v1 = v1 > 0.f ? v1 : NEG_SLOPE * v1;
        float sc = v0 * a0 + v1 * a1;
        sc += __shfl_xor_sync(0xffffffffu, sc, 1);
        sc += __shfl_xor_sync(0xffffffffu, sc, 2);
        sc += __shfl_xor_sync(0xffffffffu, sc, 4);
        float ex = __expf(sc);
        acc0 += ex * xl.x; acc1 += ex * xl.y; den += ex;
    }
    float inv = 1.f / (den + 1e-16f);
    *(float2*)(g_agg1 + (size_t)d * 64 + lane * 2) = make_float2(acc0 * inv, acc1 * inv);
}

// ---------------------------------------------------------------------------
// Fused layer-2 edge pass + head-mean + bias + relu -> final output.
// Warp per dst; lane l holds channels {8l .. 8l+7} of 256 (head h = l>>3).
// ---------------------------------------------------------------------------
__global__ void fused2_kernel(const float* __restrict__ att,
                              const float* __restrict__ bo2,
                              float* __restrict__ out) {
    int d = blockIdx.x * 8 + (threadIdx.x >> 5);
    if (d >= NN) return;
    int lane = threadIdx.x & 31;

    const float4* xrp = (const float4*)(g_xlr2 + (size_t)d * 512 + 256 + lane * 8);
    float4 xr0 = xrp[0], xr1 = xrp[1];
    float4 at0 = *(const float4*)(att + lane * 8);
    float4 at1 = *(const float4*)(att + lane * 8 + 4);

    float acc[8];
#pragma unroll
    for (int j = 0; j < 8; j++) acc[j] = 0.f;
    float den = 0.f;

    int e0 = g_off[d], e1 = g_off[d + 1];
    for (int e = e0; e < e1; e++) {
        int s = g_ssrc[e];
        const float4* xlp = (const float4*)(g_xlr2 + (size_t)s * 512 + lane * 8);
        float4 v0 = xlp[0], v1 = xlp[1];
        float t, sc = 0.f;
        t = v0.x + xr0.x; t = t > 0.f ? t : NEG_SLOPE * t; sc += t * at0.x;
        t = v0.y + xr0.y; t = t > 0.f ? t : NEG_SLOPE * t; sc += t * at0.y;
        t = v0.z + xr0.z; t = t > 0.f ? t : NEG_SLOPE * t; sc += t * at0.z;
        t = v0.w + xr0.w; t = t > 0.f ? t : NEG_SLOPE * t; sc += t * at0.w;
        t = v1.x + xr1.x; t = t > 0.f ? t : NEG_SLOPE * t; sc += t * at1.x;
        t = v1.y + xr1.y; t = t > 0.f ? t : NEG_SLOPE * t; sc += t * at1.y;
        t = v1.z + xr1.z; t = t > 0.f ? t : NEG_SLOPE * t; sc += t * at1.z;
        t = v1.w + xr1.w; t = t > 0.f ? t : NEG_SLOPE * t; sc += t * at1.w;
        sc += __shfl_xor_sync(0xffffffffu, sc, 1);
        sc += __shfl_xor_sync(0xffffffffu, sc, 2);
        sc += __shfl_xor_sync(0xffffffffu, sc, 4);
        float ex = __expf(sc);
        den += ex;
        acc[0] += ex * v0.x; acc[1] += ex * v0.y; acc[2] += ex * v0.z; acc[3] += ex * v0.w;
        acc[4] += ex * v1.x; acc[5] += ex * v1.y; acc[6] += ex * v1.z; acc[7] += ex * v1.w;
    }

    float inv = 1.f / (den + 1e-16f);
    float nv[8];
#pragma unroll
    for (int j = 0; j < 8; j++) {
        float v = acc[j] * inv;
        v += __shfl_xor_sync(0xffffffffu, v, 8);
        v += __shfl_xor_sync(0xffffffffu, v, 16);
        nv[j] = v;
    }
    if (lane < 8) {
        int c = lane * 8;
        float4 o0, o1;
        o0.x = fmaxf(0.25f * nv[0] + __ldg(bo2 + c + 0), 0.f);
        o0.y = fmaxf(0.25f * nv[1] + __ldg(bo2 + c + 1), 0.f);
        o0.z = fmaxf(0.25f * nv[2] + __ldg(bo2 + c + 2), 0.f);
        o0.w = fmaxf(0.25f * nv[3] + __ldg(bo2 + c + 3), 0.f);
        o1.x = fmaxf(0.25f * nv[4] + __ldg(bo2 + c + 4), 0.f);
        o1.y = fmaxf(0.25f * nv[5] + __ldg(bo2 + c + 5), 0.f);
        o1.z = fmaxf(0.25f * nv[6] + __ldg(bo2 + c + 6), 0.f);
        o1.w = fmaxf(0.25f * nv[7] + __ldg(bo2 + c + 7), 0.f);
        *(float4*)(out + (size_t)d * 64 + c) = o0;
        *(float4*)(out + (size_t)d * 64 + c + 4) = o1;
    }
}

// ---------------------------------------------------------------------------
// Launch
// ---------------------------------------------------------------------------
extern "C" void kernel_launch(void* const* d_in, const int* in_sizes, int n_in,
                              void* d_out, int out_size) {
    const float* x   = (const float*)d_in[0];
    const void*  ei  = d_in[1];
    // d_in[2]: frame_mask (unused)
    const float* Wl1 = (const float*)d_in[3];
    const float* bl1 = (const float*)d_in[4];
    const float* Wr1 = (const float*)d_in[5];
    const float* br1 = (const float*)d_in[6];
    const float* att1 = (const float*)d_in[7];
    const float* bo1 = (const float*)d_in[8];
    const float* Wl2 = (const float*)d_in[9];
    const float* bl2 = (const float*)d_in[10];
    const float* Wr2 = (const float*)d_in[11];
    const float* br2 = (const float*)d_in[12];
    const float* att2 = (const float*)d_in[13];
    const float* bo2 = (const float*)d_in[14];
    float* out = (float*)d_out;

    float *p_xlr1 = nullptr, *p_agg1 = nullptr, *p_xlr2 = nullptr;
    cudaGetSymbolAddress((void**)&p_xlr1, g_xlr1);
    cudaGetSymbolAddress((void**)&p_agg1, g_agg1);
    cudaGetSymbolAddress((void**)&p_xlr2, g_xlr2);

    // CSR build (sorted by dst)
    zero_meta_kernel<<<(NN + 255) / 256, 256>>>();
    detect_kernel<<<(DETECT_SAMPLES + 255) / 256, 256>>>((const long long*)ei);
    convert_hist_kernel<<<(EPE + 255) / 256, 256>>>(ei);
    scan1_kernel<<<NB, 1024>>>();
    scan2_kernel<<<1, 32>>>();
    scan3_kernel<<<NB, 1024>>>();
    scatter_kernel<<<(EPE + 255) / 256, 256>>>();

    // Layer 1
    {
        dim3 grid((NN + 31) / 32, 1);
        gemm_dual_kernel<<<grid, 256>>>(x, NN, 64, Wl1, bl1, Wr1, br1, nullptr, p_xlr1);
    }
    fused1_kernel<<<(NN + 7) / 8, 256>>>(att1);

    // Layer 2 (relu(agg1 + bo1) folded into GEMM input load)
    {
        dim3 grid((NN + 31) / 32, 4);
        gemm_dual_kernel<<<grid, 256>>>(p_agg1, NN, 256, Wl2, bl2, Wr2, br2, bo1, p_xlr2);
    }
    fused2_kernel<<<(NN + 7) / 8, 256>>>(att2, bo2, out);
}